// round 15
// baseline (speedup 1.0000x reference)
#include <cuda_runtime.h>
#include <cuda_bf16.h>
#include <cstdint>
#include <math.h>

#define BSZ 4
#define HN 16
#define LSEQ 2048
#define DM 1024
#define DH 64
#define NBH (BSZ*HN)
#define XSZ ((size_t)BSZ*LSEQ*DM)
#define WSZ ((size_t)DM*DM)

// ---------------- device scratch ----------------
__device__ __nv_bfloat16 g_xh[3*XSZ];
__device__ __nv_bfloat16 g_xl[3*XSZ];
__device__ __nv_bfloat16 g_wh[3*WSZ];
__device__ __nv_bfloat16 g_wl[3*WSZ];
__device__ __nv_bfloat16 g_qh[(size_t)NBH*LSEQ*DH];
__device__ __nv_bfloat16 g_ql[(size_t)NBH*LSEQ*DH];
__device__ __nv_bfloat16 g_kh[(size_t)NBH*LSEQ*DH];
__device__ __nv_bfloat16 g_kl[(size_t)NBH*LSEQ*DH];
__device__ __nv_bfloat16 g_vh[(size_t)NBH*LSEQ*DH];
__device__ __nv_bfloat16 g_vl[(size_t)NBH*LSEQ*DH];
__device__ float g_attn_s[(size_t)NBH*LSEQ*LSEQ];
__device__ float g_outs[(size_t)BSZ*LSEQ*DM];

// ---------------- proj smem (two pipeline stages of 4 tiles) ----------------
#define P_AH 0
#define P_AL 16384
#define P_BH 32768
#define P_BL 49152
#define PSTAGE 65536
#define SMEM_PROJ 131072

// ---------------- fused attn smem ----------------
// pass 1:
#define F_QH 0
#define F_QL 16384
#define F_KH(s) (32768 + (s)*32768)
#define F_KL(s) (49152 + (s)*32768)
// pass 2 (time-disjoint, reuses pass-1 area):
#define F_P0H 0
#define F_P0L 16384
#define F_P1H 32768
#define F_P1L 49152
#define F_VH(s) (65536 + (s)*32768)
#define F_VL(s) (81920 + (s)*32768)
// shared tail:
#define F_RS 131072           // 128 rows x 4 colgroups x f32
#define F_RINV 133120         // 128 x f32
#define SMEM_FUSED 133632

// ---------------- async copy helpers ----------------
__device__ __forceinline__ void cpasync16(uint32_t saddr, const void* g) {
    asm volatile("cp.async.cg.shared.global [%0], [%1], 16;" :: "r"(saddr), "l"(g));
}
#define CP_COMMIT()  asm volatile("cp.async.commit_group;")
#define CP_WAIT(N)   asm volatile("cp.async.wait_group %0;" :: "n"(N))

// ---------------- warp mma helpers ----------------
__device__ __forceinline__ uint32_t smem_u32(const void* p) {
    uint32_t a;
    asm("{ .reg .u64 t; cvta.to.shared.u64 t, %1; cvt.u32.u64 %0, t; }" : "=r"(a) : "l"(p));
    return a;
}
__device__ __forceinline__ uint32_t swz(uint32_t base, int r, int cb) {
    uint32_t off = (uint32_t)(r * 128 + cb);
    return base + (off ^ ((off >> 3) & 0x70));
}
__device__ __forceinline__ void ldsm4(uint32_t* r, uint32_t a) {
    asm volatile("ldmatrix.sync.aligned.m8n8.x4.shared.b16 {%0,%1,%2,%3}, [%4];"
        : "=r"(r[0]), "=r"(r[1]), "=r"(r[2]), "=r"(r[3]) : "r"(a));
}
__device__ __forceinline__ void ldsm4t(uint32_t* r, uint32_t a) {
    asm volatile("ldmatrix.sync.aligned.m8n8.x4.trans.shared.b16 {%0,%1,%2,%3}, [%4];"
        : "=r"(r[0]), "=r"(r[1]), "=r"(r[2]), "=r"(r[3]) : "r"(a));
}
__device__ __forceinline__ void mma16816(float* c, const uint32_t* a, const uint32_t* b) {
    asm volatile("mma.sync.aligned.m16n8k16.row.col.f32.bf16.bf16.f32 "
        "{%0,%1,%2,%3}, {%4,%5,%6,%7}, {%8,%9}, {%0,%1,%2,%3};"
        : "+f"(c[0]), "+f"(c[1]), "+f"(c[2]), "+f"(c[3])
        : "r"(a[0]), "r"(a[1]), "r"(a[2]), "r"(a[3]), "r"(b[0]), "r"(b[1]));
}

// ---------------- math helpers ----------------
__device__ __forceinline__ void split2(float a, float b, uint32_t& hp, uint32_t& lp) {
    __nv_bfloat16 ah = __float2bfloat16(a), bh = __float2bfloat16(b);
    float al = a - __bfloat162float(ah);
    float bl = b - __bfloat162float(bh);
    __nv_bfloat162 hv; hv.x = ah; hv.y = bh;
    __nv_bfloat162 lv; lv.x = __float2bfloat16(al); lv.y = __float2bfloat16(bl);
    hp = *reinterpret_cast<uint32_t*>(&hv);
    lp = *reinterpret_cast<uint32_t*>(&lv);
}
__device__ __forceinline__ float fast_exp8(float raw) {
    float y = raw * 0.180336880090206f;          // (1/8)*log2(e)
    int n = __float2int_rn(y);
    float f = y - (float)n;
    float p = 1.54035304e-4f;
    p = fmaf(p, f, 1.33335581e-3f);
    p = fmaf(p, f, 9.61812911e-3f);
    p = fmaf(p, f, 5.55041087e-2f);
    p = fmaf(p, f, 2.40226507e-1f);
    p = fmaf(p, f, 6.93147181e-1f);
    p = fmaf(p, f, 1.0f);
    return p * __int_as_float((n + 127) << 23);
}

// ===========================================================================
// convert_all: 6 tensors, 4 independent float4 per thread (MLP=4).
// grid (2048, 6): y 0-2 = X, y 3-5 = W (only first 256 x-blocks active).
// ===========================================================================
__global__ void convert_all_kernel(
    const float* __restrict__ s0, const float* __restrict__ s1, const float* __restrict__ s2,
    const float* __restrict__ s3, const float* __restrict__ s4, const float* __restrict__ s5,
    __nv_bfloat16* __restrict__ xh, __nv_bfloat16* __restrict__ xl,
    __nv_bfloat16* __restrict__ wh, __nv_bfloat16* __restrict__ wl)
{
    const int y = blockIdx.y;
    const float* srcs[6] = {s0, s1, s2, s3, s4, s5};
    const float* src = srcs[y];
    __nv_bfloat16 *hi, *lo;
    int n4;
    if (y < 3) { hi = xh + (size_t)y * XSZ; lo = xl + (size_t)y * XSZ; n4 = (int)(XSZ / 4); }
    else       { hi = wh + (size_t)(y - 3) * WSZ; lo = wl + (size_t)(y - 3) * WSZ; n4 = (int)(WSZ / 4); }

    if (blockIdx.x * 1024 >= n4) return;   // sizes are exact multiples of 1024
    const int base = blockIdx.x * 1024 + threadIdx.x;

    float4 v[4];
#pragma unroll
    for (int k = 0; k < 4; k++)
        v[k] = reinterpret_cast<const float4*>(src)[base + k * 256];
#pragma unroll
    for (int k = 0; k < 4; k++) {
        uint32_t h0, l0, h1, l1;
        split2(v[k].x, v[k].y, h0, l0);
        split2(v[k].z, v[k].w, h1, l1);
        reinterpret_cast<uint2*>(hi)[base + k * 256] = make_uint2(h0, h1);
        reinterpret_cast<uint2*>(lo)[base + k * 256] = make_uint2(l0, l1);
    }
}

// ===========================================================================
// 64x32 warp-tile MMA (8 warps / 256 thr over 128x128), K-chunk 64, 3 terms.
// ===========================================================================
__device__ __forceinline__ void mma_block_64(
    float C[4][4][4], uint32_t ah, uint32_t al, uint32_t bh, uint32_t bl,
    int m_base, int n_base, int lane)
{
#pragma unroll
    for (int term = 0; term < 3; term++) {
        uint32_t As = (term == 2) ? al : ah;
        uint32_t Bs = (term == 1) ? bl : bh;
#pragma unroll
        for (int ks = 0; ks < 4; ks++) {
            uint32_t a[4][4];
#pragma unroll
            for (int mt = 0; mt < 4; mt++)
                ldsm4(a[mt], swz(As, m_base + mt * 16 + (lane & 15), ks * 32 + (lane >> 4) * 16));
            uint32_t b[4][2];
            const int mg = lane >> 3, rs = lane & 7;
#pragma unroll
            for (int p = 0; p < 2; p++) {
                uint32_t r4[4];
                int row = n_base + p * 16 + ((mg >= 2) ? 8 : 0) + rs;
                int cb = ks * 32 + (mg & 1) * 16;
                ldsm4(r4, swz(Bs, row, cb));
                b[2 * p][0] = r4[0]; b[2 * p][1] = r4[1];
                b[2 * p + 1][0] = r4[2]; b[2 * p + 1][1] = r4[3];
            }
#pragma unroll
            for (int mt = 0; mt < 4; mt++)
#pragma unroll
                for (int nt = 0; nt < 4; nt++)
                    mma16816(C[mt][nt], a[mt], b[nt]);
        }
    }
}

// ===========================================================================
// 32x32 warp-tile MMA (16 warps / 512 thr over 128x128), K-chunk 64, 3 terms.
// ===========================================================================
__device__ __forceinline__ void mma_block_32(
    float C[2][4][4], uint32_t ah, uint32_t al, uint32_t bh, uint32_t bl,
    int m_base, int n_base, int lane)
{
#pragma unroll
    for (int term = 0; term < 3; term++) {
        uint32_t As = (term == 2) ? al : ah;
        uint32_t Bs = (term == 1) ? bl : bh;
#pragma unroll
        for (int ks = 0; ks < 4; ks++) {
            uint32_t a[2][4];
#pragma unroll
            for (int mt = 0; mt < 2; mt++)
                ldsm4(a[mt], swz(As, m_base + mt * 16 + (lane & 15), ks * 32 + (lane >> 4) * 16));
            uint32_t b[4][2];
            const int mg = lane >> 3, rs = lane & 7;
#pragma unroll
            for (int p = 0; p < 2; p++) {
                uint32_t r4[4];
                int row = n_base + p * 16 + ((mg >= 2) ? 8 : 0) + rs;
                int cb = ks * 32 + (mg & 1) * 16;
                ldsm4(r4, swz(Bs, row, cb));
                b[2 * p][0] = r4[0]; b[2 * p][1] = r4[1];
                b[2 * p + 1][0] = r4[2]; b[2 * p + 1][1] = r4[3];
            }
#pragma unroll
            for (int mt = 0; mt < 2; mt++)
#pragma unroll
                for (int nt = 0; nt < 4; nt++)
                    mma16816(C[mt][nt], a[mt], b[nt]);
        }
    }
}

// ===========================================================================
// Stage A: all 3 projections (256 thr, 2x4 warps, 64x32 tiles).
// ===========================================================================
__global__ void __launch_bounds__(256) proj_kernel(
    const __nv_bfloat16* __restrict__ xh_all, const __nv_bfloat16* __restrict__ xl_all,
    const __nv_bfloat16* __restrict__ wh_all, const __nv_bfloat16* __restrict__ wl_all,
    __nv_bfloat16* __restrict__ qh, __nv_bfloat16* __restrict__ ql,
    __nv_bfloat16* __restrict__ kh, __nv_bfloat16* __restrict__ kl,
    __nv_bfloat16* __restrict__ vh, __nv_bfloat16* __restrict__ vl)
{
    extern __shared__ char smem[];
    const uint32_t sb = smem_u32(smem);
    const int tid = threadIdx.x, wid = tid >> 5, lane = tid & 31;
    const int n0 = blockIdx.x * 128, m0 = blockIdx.y * 128;
    const int z = blockIdx.z;
    const int m_base = (wid & 1) * 64, n_base = (wid >> 1) * 32;

    const __nv_bfloat16* xh = xh_all + (size_t)z * XSZ;
    const __nv_bfloat16* xl = xl_all + (size_t)z * XSZ;
    const __nv_bfloat16* wh = wh_all + (size_t)z * WSZ;
    const __nv_bfloat16* wl = wl_all + (size_t)z * WSZ;
    __nv_bfloat16* oh = (z == 0) ? qh : (z == 1) ? kh : vh;
    __nv_bfloat16* ol = (z == 0) ? ql : (z == 1) ? kl : vl;

    auto load_chunk = [&](int ck, int stage) {
        const int k0 = ck * 64;
        const uint32_t st = sb + stage * PSTAGE;
        for (int i = tid; i < 1024; i += 256) {
            int r = i >> 3, c8 = (i & 7) * 8;
            uint32_t d = swz((uint32_t)0, r, c8 * 2);
            size_t ga = (size_t)(m0 + r) * DM + k0 + c8;
            size_t gb = (size_t)(n0 + r) * DM + k0 + c8;
            cpasync16(st + P_AH + d, &xh[ga]);
            cpasync16(st + P_AL + d, &xl[ga]);
            cpasync16(st + P_BH + d, &wh[gb]);
            cpasync16(st + P_BL + d, &wl[gb]);
        }
        CP_COMMIT();
    };

    float C[4][4][4] = {};
    load_chunk(0, 0);
    for (int ck = 0; ck < 16; ck++) {
        const int stage = ck & 1;
        if (ck + 1 < 16) { load_chunk(ck + 1, (ck + 1) & 1); CP_WAIT(1); }
        else             { CP_WAIT(0); }
        __syncthreads();
        const uint32_t st = sb + stage * PSTAGE;
        mma_block_64(C, st + P_AH, st + P_AL, st + P_BH, st + P_BL, m_base, n_base, lane);
        __syncthreads();
    }

#pragma unroll
    for (int mt = 0; mt < 4; mt++) {
#pragma unroll
        for (int nt = 0; nt < 4; nt++) {
            int n = n0 + n_base + nt * 8 + 2 * (lane & 3);
            int h = n >> 6, dd = n & 63;
#pragma unroll
            for (int half = 0; half < 2; half++) {
                int m = m0 + m_base + mt * 16 + (lane >> 2) + half * 8;
                int b = m >> 11, l = m & (LSEQ - 1);
                uint32_t hp, lp;
                split2(C[mt][nt][half * 2], C[mt][nt][half * 2 + 1], hp, lp);
                size_t base = (((size_t)(b * HN + h)) * LSEQ + l) * DH + dd;
                *reinterpret_cast<uint32_t*>(&oh[base]) = hp;
                *reinterpret_cast<uint32_t*>(&ol[base]) = lp;
            }
        }
    }
}

// ===========================================================================
// Fused attention: per block = (bh, 128 q-rows). 512 thr (16 warps).
// Pass 1: E = exp(QK^T/8) -> attn (raw) + reg rowsums. K dbl-buffered.
// Pass 2: K-chunks of 128 — read E (L2-hot), normalize in place, O = P@V.
// ===========================================================================
__global__ void __launch_bounds__(512) attn_fused_kernel(
    const __nv_bfloat16* __restrict__ qh, const __nv_bfloat16* __restrict__ ql,
    const __nv_bfloat16* __restrict__ kh, const __nv_bfloat16* __restrict__ kl,
    const __nv_bfloat16* __restrict__ vh, const __nv_bfloat16* __restrict__ vl,
    float* __restrict__ attn, float* __restrict__ out)
{
    extern __shared__ char smem[];
    const uint32_t sb = smem_u32(smem);
    const int tid = threadIdx.x, wid = tid >> 5, lane = tid & 31;
    const int mt_blk = blockIdx.x, bh = blockIdx.y;
    const int m0 = mt_blk * 128;

    const __nv_bfloat16* qhb = qh + ((size_t)bh * LSEQ + m0) * DH;
    const __nv_bfloat16* qlb = ql + ((size_t)bh * LSEQ + m0) * DH;
    const __nv_bfloat16* khb = kh + (size_t)bh * LSEQ * DH;
    const __nv_bfloat16* klb = kl + (size_t)bh * LSEQ * DH;
    const __nv_bfloat16* vhb = vh + (size_t)bh * LSEQ * DH;
    const __nv_bfloat16* vlb = vl + (size_t)bh * LSEQ * DH;
    float* apb = attn + ((size_t)bh * LSEQ + m0) * LSEQ;

    // ---- load Q + K(0) ----
    auto load_k = [&](int nt, int stage) {
        const int n0 = nt * 128;
        for (int i = tid; i < 1024; i += 512) {
            int r = i >> 3, c8 = (i & 7) * 8;
            uint32_t d = swz((uint32_t)0, r, c8 * 2);
            size_t ga = (size_t)(n0 + r) * DH + c8;
            cpasync16(sb + F_KH(stage) + d, &khb[ga]);
            cpasync16(sb + F_KL(stage) + d, &klb[ga]);
        }
        CP_COMMIT();
    };
    for (int i = tid; i < 1024; i += 512) {
        int r = i >> 3, c8 = (i & 7) * 8;
        uint32_t d = swz((uint32_t)0, r, c8 * 2);
        size_t ga = (size_t)r * DH + c8;
        cpasync16(sb + F_QH + d, &qhb[ga]);
        cpasync16(sb + F_QL + d, &qlb[ga]);
    }
    load_k(0, 0);

    // ---- Pass 1: 16 N-tiles ----
    const int m_base = (wid & 3) * 32, n_base = (wid >> 2) * 32;
    float sloc[2][2] = {};

    for (int nt = 0; nt < 16; nt++) {
        const int stage = nt & 1;
        if (nt + 1 < 16) { load_k(nt + 1, stage ^ 1); CP_WAIT(1); }
        else             { CP_WAIT(0); }
        __syncthreads();

        float C1[2][4][4] = {};
        mma_block_32(C1, sb + F_QH, sb + F_QL, sb + F_KH(stage), sb + F_KL(stage),
                     m_base, n_base, lane);

        const int n0 = nt * 128;
#pragma unroll
        for (int mt = 0; mt < 2; mt++)
#pragma unroll
            for (int ni = 0; ni < 4; ni++)
#pragma unroll
                for (int half = 0; half < 2; half++) {
                    float e0 = fast_exp8(C1[mt][ni][half * 2]);
                    float e1 = fast_exp8(C1[mt][ni][half * 2 + 1]);
                    sloc[mt][half] += e0 + e1;
                    int row = m_base + mt * 16 + (lane >> 2) + half * 8;
                    int col = n0 + n_base + ni * 8 + 2 * (lane & 3);
                    *reinterpret_cast<float2*>(&apb[(size_t)row * LSEQ + col]) =
                        make_float2(e0, e1);
                }
        __syncthreads();
    }

    // ---- rowsum ----
    float* RS = reinterpret_cast<float*>(smem + F_RS);
#pragma unroll
    for (int mt = 0; mt < 2; mt++)
#pragma unroll
        for (int half = 0; half < 2; half++) {
            float v = sloc[mt][half];
            v += __shfl_xor_sync(0xFFFFFFFFu, v, 1);
            v += __shfl_xor_sync(0xFFFFFFFFu, v, 2);
            if ((lane & 3) == 0) {
                int row = m_base + mt * 16 + (lane >> 2) + half * 8;
                RS[row * 4 + (wid >> 2)] = v;
            }
        }
    __syncthreads();
    float* srinv = reinterpret_cast<float*>(smem + F_RINV);
    if (tid < 128) {
        float s = RS[tid * 4 + 0] + RS[tid * 4 + 1] + RS[tid * 4 + 2] + RS[tid * 4 + 3];
        srinv[tid] = 1.0f / s;
    }
    __syncthreads();

    // ---- Pass 2: 16 K-chunks of 128 ----
    const int n_base2 = (wid >> 2) * 16;   // m_base reused
    const int er = tid >> 4, ec = (tid & 15) * 4;

    auto load_v = [&](int ck, int stage) {
        const int k0 = ck * 128;
        for (int i = tid; i < 1024; i += 512) {
            int r = i >> 3, c8 = (i & 7) * 8;
            uint32_t d = swz((uint32_t)0, r, c8 * 2);
            size_t ga = (size_t)(k0 + r) * DH + c8;
            cpasync16(sb + F_VH(stage) + d, &vhb[ga]);
            cpasync16(sb + F_VL(stage) + d, &vlb[ga]);
        }
        CP_COMMIT();
    };

    float4 Ereg[8];
#pragma unroll
    for (int j = 0; j < 4; j++)
#pragma unroll
        for (int h = 0; h < 2; h++)
            Ereg[j * 2 + h] = *reinterpret_cast<const float4*>(
                &apb[(size_t)(er + j * 32) * LSEQ + h * 64 + ec]);
    load_v(0, 0);

    float C2[2][2][4] = {};

    for (int ck = 0; ck < 16; ck++) {
        const int k0 = ck * 128;
        const int stage = ck & 1;
        if (ck + 1 < 16) load_v(ck + 1, stage ^ 1);

        // normalize current E chunk (regs), write final attn, split to P tiles
#pragma unroll
        for (int j = 0; j < 4; j++) {
            int r = er + j * 32;
            float ri = srinv[r];
#pragma unroll
            for (int h = 0; h < 2; h++) {
                float4 e = Ereg[j * 2 + h];
                e.x *= ri; e.y *= ri; e.z *= ri; e.w *= ri;
                *reinterpret_cast<float4*>(&apb[(size_t)r * LSEQ + k0 + h * 64 + ec]) = e;
                uint32_t h0, l0, h1, l1;
                split2(e.x, e.y, h0, l0);
                split2(e.z, e.w, h1, l1);
                uint32_t d = swz((uint32_t)0, r, ec * 2);
                *reinterpret_cast<uint2*>(smem + (h ? F_P1H : F_P0H) + d) = make_uint2(h0, h1);
                *reinterpret_cast<uint2*>(smem + (h ? F_P1L : F_P0L) + d) = make_uint2(l0, l1);
            }
        }
        if (ck + 1 < 16) { CP_WAIT(1); } else { CP_WAIT(0); }
        __syncthreads();

        // prefetch next E chunk (hidden by MMA)
        if (ck + 1 < 16) {
#pragma unroll
            for (int j = 0; j < 4; j++)
#pragma unroll
                for (int h = 0; h < 2; h++)
                    Ereg[j * 2 + h] = *reinterpret_cast<const float4*>(
                        &apb[(size_t)(er + j * 32) * LSEQ + (k0 + 128) + h * 64 + ec]);
        }

        const uint32_t vH = sb + F_VH(stage), vL = sb + F_VL(stage);
#pragma unroll
        for (int term = 0; term < 3; term++) {
#pragma unroll
            for (int ks = 0; ks < 8; ks++) {
                const int ksl = ks & 3;
                uint32_t As;
                if (term == 2) As = sb + ((ks < 4) ? F_P0L : F_P1L);
                else           As = sb + ((ks < 4) ? F_P0H : F_P1H);
                uint32_t Bs = (term == 1) ? vL : vH;
                uint32_t a[2][4];
#pragma unroll
                for (int mt = 0; mt < 2; mt++)
                    ldsm4(a[mt], swz(As, m_base + mt * 16 + (lane & 15), ksl * 32 + (lane >> 4) * 16));
                uint32_t b[2][2];
                const int mg = lane >> 3, rs = lane & 7;
                {
                    uint32_t r4[4];
                    int row = ks * 16 + (mg & 1) * 8 + rs;
                    int cb = (n_base2 + ((mg >= 2) ? 8 : 0)) * 2;
                    ldsm4t(r4, swz(Bs, row, cb));
                    b[0][0] = r4[0]; b[0][1] = r4[1];
                    b[1][0] = r4[2]; b[1][1] = r4[3];
                }
#pragma unroll
                for (int mt = 0; mt < 2; mt++)
#pragma unroll
                    for (int nt = 0; nt < 2; nt++)
                        mma16816(C2[mt][nt], a[mt], b[nt]);
            }
        }
        __syncthreads();
    }

    const int b = bh >> 4, h = bh & 15;
#pragma unroll
    for (int mt = 0; mt < 2; mt++)
#pragma unroll
        for (int nt = 0; nt < 2; nt++) {
            int n = n_base2 + nt * 8 + 2 * (lane & 3);
#pragma unroll
            for (int half = 0; half < 2; half++) {
                int m = m0 + m_base + mt * 16 + (lane >> 2) + half * 8;
                *reinterpret_cast<float2*>(&out[((size_t)b * LSEQ + m) * DM + h * DH + n]) =
                    make_float2(C2[mt][nt][half * 2], C2[mt][nt][half * 2 + 1]);
            }
        }
}

// ===========================================================================
extern "C" void kernel_launch(void* const* d_in, const int* in_sizes, int n_in,
                              void* d_out, int out_size) {
    const float* q_in = (const float*)d_in[0];
    const float* k_in = (const float*)d_in[1];
    const float* v_in = (const float*)d_in[2];
    const float* wq   = (const float*)d_in[3];
    const float* wk   = (const float*)d_in[4];
    const float* wv   = (const float*)d_in[5];

    __nv_bfloat16 *xh, *xl, *wh, *wl, *qh, *ql, *kh, *kl, *vh, *vl;
    float *attn_scratch, *out_scratch;
    cudaGetSymbolAddress((void**)&xh, g_xh);
    cudaGetSymbolAddress((void**)&xl, g_xl);
    cudaGetSymbolAddress((void**)&wh, g_wh);
    cudaGetSymbolAddress((void**)&wl, g_wl);
    cudaGetSymbolAddress((void**)&qh, g_qh);
    cudaGetSymbolAddress((void**)&ql, g_ql);
    cudaGetSymbolAddress((void**)&kh, g_kh);
    cudaGetSymbolAddress((void**)&kl, g_kl);
    cudaGetSymbolAddress((void**)&vh, g_vh);
    cudaGetSymbolAddress((void**)&vl, g_vl);
    cudaGetSymbolAddress((void**)&attn_scratch, g_attn_s);
    cudaGetSymbolAddress((void**)&out_scratch, g_outs);

    const long long out_elems  = (long long)BSZ * LSEQ * DM;
    const long long attn_elems = (long long)NBH * LSEQ * LSEQ;

    float* out_ptr  = (float*)d_out;
    float* attn_ptr = attn_scratch;
    long long osz = (long long)out_size;
    if (osz >= out_elems + attn_elems) {
        attn_ptr = (float*)d_out + out_elems;
    } else if (osz == attn_elems) {
        attn_ptr = (float*)d_out;
        out_ptr  = out_scratch;
    }

    cudaFuncSetAttribute(proj_kernel,       cudaFuncAttributeMaxDynamicSharedMemorySize, SMEM_PROJ);
    cudaFuncSetAttribute(attn_fused_kernel, cudaFuncAttributeMaxDynamicSharedMemorySize, SMEM_FUSED);

    convert_all_kernel<<<dim3(2048, 6), 256>>>(
        q_in, k_in, v_in, wq, wk, wv, xh, xl, wh, wl);

    proj_kernel<<<dim3(DM / 128, (BSZ * LSEQ) / 128, 3), 256, SMEM_PROJ>>>(
        xh, xl, wh, wl, qh, ql, kh, kl, vh, vl);

    attn_fused_kernel<<<dim3(16, NBH), 512, SMEM_FUSED>>>(
        qh, ql, kh, kl, vh, vl, attn_ptr, out_ptr);
}

// round 17
// speedup vs baseline: 1.2509x; 1.2509x over previous
#include <cuda_runtime.h>
#include <cuda_bf16.h>
#include <cstdint>
#include <math.h>

#define BSZ 4
#define HN 16
#define LSEQ 2048
#define DM 1024
#define DH 64
#define NBH (BSZ*HN)
#define XSZ ((size_t)BSZ*LSEQ*DM)
#define WSZ ((size_t)DM*DM)

// ---------------- device scratch ----------------
__device__ __nv_bfloat16 g_xh[3*XSZ];
__device__ __nv_bfloat16 g_xl[3*XSZ];
__device__ __nv_bfloat16 g_wh[3*WSZ];
__device__ __nv_bfloat16 g_wl[3*WSZ];
__device__ __nv_bfloat16 g_qh[(size_t)NBH*LSEQ*DH];
__device__ __nv_bfloat16 g_ql[(size_t)NBH*LSEQ*DH];
__device__ __nv_bfloat16 g_kh[(size_t)NBH*LSEQ*DH];
__device__ __nv_bfloat16 g_kl[(size_t)NBH*LSEQ*DH];
__device__ __nv_bfloat16 g_vh[(size_t)NBH*LSEQ*DH];
__device__ __nv_bfloat16 g_vl[(size_t)NBH*LSEQ*DH];
__device__ float g_attn_s[(size_t)NBH*LSEQ*LSEQ];
__device__ float g_outs[(size_t)BSZ*LSEQ*DM];

// ---------------- proj smem (two pipeline stages of 4 tiles) ----------------
#define P_AH 0
#define P_AL 16384
#define P_BH 32768
#define P_BL 49152
#define PSTAGE 65536
#define SMEM_PROJ 131072

// ---------------- fused attn smem (R13-proven layout) ----------------
#define F_QH 0
#define F_QL 16384
#define F_KH(s) (32768 + (s)*32768)
#define F_KL(s) (49152 + (s)*32768)
// pass 2 reuses K area:
#define F_PH 32768
#define F_PL 49152
#define F_VH(s) (65536 + (s)*16384)
#define F_VL(s) (73728 + (s)*16384)
#define F_RS 98304            // 128 rows x 4 colgroups x f32
#define F_RINV 100352         // 128 x f32
#define SMEM_FUSED 100864

// ---------------- async copy helpers ----------------
__device__ __forceinline__ void cpasync16(uint32_t saddr, const void* g) {
    asm volatile("cp.async.cg.shared.global [%0], [%1], 16;" :: "r"(saddr), "l"(g));
}
#define CP_COMMIT()  asm volatile("cp.async.commit_group;")
#define CP_WAIT(N)   asm volatile("cp.async.wait_group %0;" :: "n"(N))

// ---------------- warp mma helpers ----------------
__device__ __forceinline__ uint32_t smem_u32(const void* p) {
    uint32_t a;
    asm("{ .reg .u64 t; cvta.to.shared.u64 t, %1; cvt.u32.u64 %0, t; }" : "=r"(a) : "l"(p));
    return a;
}
__device__ __forceinline__ uint32_t swz(uint32_t base, int r, int cb) {
    uint32_t off = (uint32_t)(r * 128 + cb);
    return base + (off ^ ((off >> 3) & 0x70));
}
__device__ __forceinline__ void ldsm4(uint32_t* r, uint32_t a) {
    asm volatile("ldmatrix.sync.aligned.m8n8.x4.shared.b16 {%0,%1,%2,%3}, [%4];"
        : "=r"(r[0]), "=r"(r[1]), "=r"(r[2]), "=r"(r[3]) : "r"(a));
}
__device__ __forceinline__ void ldsm4t(uint32_t* r, uint32_t a) {
    asm volatile("ldmatrix.sync.aligned.m8n8.x4.trans.shared.b16 {%0,%1,%2,%3}, [%4];"
        : "=r"(r[0]), "=r"(r[1]), "=r"(r[2]), "=r"(r[3]) : "r"(a));
}
__device__ __forceinline__ void mma16816(float* c, const uint32_t* a, const uint32_t* b) {
    asm volatile("mma.sync.aligned.m16n8k16.row.col.f32.bf16.bf16.f32 "
        "{%0,%1,%2,%3}, {%4,%5,%6,%7}, {%8,%9}, {%0,%1,%2,%3};"
        : "+f"(c[0]), "+f"(c[1]), "+f"(c[2]), "+f"(c[3])
        : "r"(a[0]), "r"(a[1]), "r"(a[2]), "r"(a[3]), "r"(b[0]), "r"(b[1]));
}

// ---------------- math helpers ----------------
__device__ __forceinline__ void split2(float a, float b, uint32_t& hp, uint32_t& lp) {
    __nv_bfloat16 ah = __float2bfloat16(a), bh = __float2bfloat16(b);
    float al = a - __bfloat162float(ah);
    float bl = b - __bfloat162float(bh);
    __nv_bfloat162 hv; hv.x = ah; hv.y = bh;
    __nv_bfloat162 lv; lv.x = __float2bfloat16(al); lv.y = __float2bfloat16(bl);
    hp = *reinterpret_cast<uint32_t*>(&hv);
    lp = *reinterpret_cast<uint32_t*>(&lv);
}
__device__ __forceinline__ float fast_exp8(float raw) {
    float y = raw * 0.180336880090206f;          // (1/8)*log2(e)
    int n = __float2int_rn(y);
    float f = y - (float)n;
    float p = 1.54035304e-4f;
    p = fmaf(p, f, 1.33335581e-3f);
    p = fmaf(p, f, 9.61812911e-3f);
    p = fmaf(p, f, 5.55041087e-2f);
    p = fmaf(p, f, 2.40226507e-1f);
    p = fmaf(p, f, 6.93147181e-1f);
    p = fmaf(p, f, 1.0f);
    return p * __int_as_float((n + 127) << 23);
}

// ===========================================================================
// convert_all: 6 tensors, 4 independent float4 per thread (MLP=4).
// grid (2048, 6): y 0-2 = X, y 3-5 = W (only first 256 x-blocks active).
// ===========================================================================
__global__ void convert_all_kernel(
    const float* __restrict__ s0, const float* __restrict__ s1, const float* __restrict__ s2,
    const float* __restrict__ s3, const float* __restrict__ s4, const float* __restrict__ s5,
    __nv_bfloat16* __restrict__ xh, __nv_bfloat16* __restrict__ xl,
    __nv_bfloat16* __restrict__ wh, __nv_bfloat16* __restrict__ wl)
{
    const int y = blockIdx.y;
    const float* srcs[6] = {s0, s1, s2, s3, s4, s5};
    const float* src = srcs[y];
    __nv_bfloat16 *hi, *lo;
    int n4;
    if (y < 3) { hi = xh + (size_t)y * XSZ; lo = xl + (size_t)y * XSZ; n4 = (int)(XSZ / 4); }
    else       { hi = wh + (size_t)(y - 3) * WSZ; lo = wl + (size_t)(y - 3) * WSZ; n4 = (int)(WSZ / 4); }

    if (blockIdx.x * 1024 >= n4) return;   // sizes are exact multiples of 1024
    const int base = blockIdx.x * 1024 + threadIdx.x;

    float4 v[4];
#pragma unroll
    for (int k = 0; k < 4; k++)
        v[k] = reinterpret_cast<const float4*>(src)[base + k * 256];
#pragma unroll
    for (int k = 0; k < 4; k++) {
        uint32_t h0, l0, h1, l1;
        split2(v[k].x, v[k].y, h0, l0);
        split2(v[k].z, v[k].w, h1, l1);
        reinterpret_cast<uint2*>(hi)[base + k * 256] = make_uint2(h0, h1);
        reinterpret_cast<uint2*>(lo)[base + k * 256] = make_uint2(l0, l1);
    }
}

// ===========================================================================
// 64x32 warp-tile MMA (8 warps / 256 thr over 128x128), K-chunk 64, 3 terms.
// ===========================================================================
__device__ __forceinline__ void mma_block_64(
    float C[4][4][4], uint32_t ah, uint32_t al, uint32_t bh, uint32_t bl,
    int m_base, int n_base, int lane)
{
#pragma unroll
    for (int term = 0; term < 3; term++) {
        uint32_t As = (term == 2) ? al : ah;
        uint32_t Bs = (term == 1) ? bl : bh;
#pragma unroll
        for (int ks = 0; ks < 4; ks++) {
            uint32_t a[4][4];
#pragma unroll
            for (int mt = 0; mt < 4; mt++)
                ldsm4(a[mt], swz(As, m_base + mt * 16 + (lane & 15), ks * 32 + (lane >> 4) * 16));
            uint32_t b[4][2];
            const int mg = lane >> 3, rs = lane & 7;
#pragma unroll
            for (int p = 0; p < 2; p++) {
                uint32_t r4[4];
                int row = n_base + p * 16 + ((mg >= 2) ? 8 : 0) + rs;
                int cb = ks * 32 + (mg & 1) * 16;
                ldsm4(r4, swz(Bs, row, cb));
                b[2 * p][0] = r4[0]; b[2 * p][1] = r4[1];
                b[2 * p + 1][0] = r4[2]; b[2 * p + 1][1] = r4[3];
            }
#pragma unroll
            for (int mt = 0; mt < 4; mt++)
#pragma unroll
                for (int nt = 0; nt < 4; nt++)
                    mma16816(C[mt][nt], a[mt], b[nt]);
        }
    }
}

// ===========================================================================
// 32x32 warp-tile MMA (16 warps / 512 thr over 128x128), K-chunk 64, 3 terms.
// ===========================================================================
__device__ __forceinline__ void mma_block_32(
    float C[2][4][4], uint32_t ah, uint32_t al, uint32_t bh, uint32_t bl,
    int m_base, int n_base, int lane)
{
#pragma unroll
    for (int term = 0; term < 3; term++) {
        uint32_t As = (term == 2) ? al : ah;
        uint32_t Bs = (term == 1) ? bl : bh;
#pragma unroll
        for (int ks = 0; ks < 4; ks++) {
            uint32_t a[2][4];
#pragma unroll
            for (int mt = 0; mt < 2; mt++)
                ldsm4(a[mt], swz(As, m_base + mt * 16 + (lane & 15), ks * 32 + (lane >> 4) * 16));
            uint32_t b[4][2];
            const int mg = lane >> 3, rs = lane & 7;
#pragma unroll
            for (int p = 0; p < 2; p++) {
                uint32_t r4[4];
                int row = n_base + p * 16 + ((mg >= 2) ? 8 : 0) + rs;
                int cb = ks * 32 + (mg & 1) * 16;
                ldsm4(r4, swz(Bs, row, cb));
                b[2 * p][0] = r4[0]; b[2 * p][1] = r4[1];
                b[2 * p + 1][0] = r4[2]; b[2 * p + 1][1] = r4[3];
            }
#pragma unroll
            for (int mt = 0; mt < 2; mt++)
#pragma unroll
                for (int nt = 0; nt < 4; nt++)
                    mma16816(C[mt][nt], a[mt], b[nt]);
        }
    }
}

// ===========================================================================
// Stage A: all 3 projections (256 thr, 2x4 warps, 64x32 tiles).
// ===========================================================================
__global__ void __launch_bounds__(256) proj_kernel(
    const __nv_bfloat16* __restrict__ xh_all, const __nv_bfloat16* __restrict__ xl_all,
    const __nv_bfloat16* __restrict__ wh_all, const __nv_bfloat16* __restrict__ wl_all,
    __nv_bfloat16* __restrict__ qh, __nv_bfloat16* __restrict__ ql,
    __nv_bfloat16* __restrict__ kh, __nv_bfloat16* __restrict__ kl,
    __nv_bfloat16* __restrict__ vh, __nv_bfloat16* __restrict__ vl)
{
    extern __shared__ char smem[];
    const uint32_t sb = smem_u32(smem);
    const int tid = threadIdx.x, wid = tid >> 5, lane = tid & 31;
    const int n0 = blockIdx.x * 128, m0 = blockIdx.y * 128;
    const int z = blockIdx.z;
    const int m_base = (wid & 1) * 64, n_base = (wid >> 1) * 32;

    const __nv_bfloat16* xh = xh_all + (size_t)z * XSZ;
    const __nv_bfloat16* xl = xl_all + (size_t)z * XSZ;
    const __nv_bfloat16* wh = wh_all + (size_t)z * WSZ;
    const __nv_bfloat16* wl = wl_all + (size_t)z * WSZ;
    __nv_bfloat16* oh = (z == 0) ? qh : (z == 1) ? kh : vh;
    __nv_bfloat16* ol = (z == 0) ? ql : (z == 1) ? kl : vl;

    auto load_chunk = [&](int ck, int stage) {
        const int k0 = ck * 64;
        const uint32_t st = sb + stage * PSTAGE;
        for (int i = tid; i < 1024; i += 256) {
            int r = i >> 3, c8 = (i & 7) * 8;
            uint32_t d = swz((uint32_t)0, r, c8 * 2);
            size_t ga = (size_t)(m0 + r) * DM + k0 + c8;
            size_t gb = (size_t)(n0 + r) * DM + k0 + c8;
            cpasync16(st + P_AH + d, &xh[ga]);
            cpasync16(st + P_AL + d, &xl[ga]);
            cpasync16(st + P_BH + d, &wh[gb]);
            cpasync16(st + P_BL + d, &wl[gb]);
        }
        CP_COMMIT();
    };

    float C[4][4][4] = {};
    load_chunk(0, 0);
    for (int ck = 0; ck < 16; ck++) {
        const int stage = ck & 1;
        if (ck + 1 < 16) { load_chunk(ck + 1, (ck + 1) & 1); CP_WAIT(1); }
        else             { CP_WAIT(0); }
        __syncthreads();
        const uint32_t st = sb + stage * PSTAGE;
        mma_block_64(C, st + P_AH, st + P_AL, st + P_BH, st + P_BL, m_base, n_base, lane);
        __syncthreads();
    }

#pragma unroll
    for (int mt = 0; mt < 4; mt++) {
#pragma unroll
        for (int nt = 0; nt < 4; nt++) {
            int n = n0 + n_base + nt * 8 + 2 * (lane & 3);
            int h = n >> 6, dd = n & 63;
#pragma unroll
            for (int half = 0; half < 2; half++) {
                int m = m0 + m_base + mt * 16 + (lane >> 2) + half * 8;
                int b = m >> 11, l = m & (LSEQ - 1);
                uint32_t hp, lp;
                split2(C[mt][nt][half * 2], C[mt][nt][half * 2 + 1], hp, lp);
                size_t base = (((size_t)(b * HN + h)) * LSEQ + l) * DH + dd;
                *reinterpret_cast<uint32_t*>(&oh[base]) = hp;
                *reinterpret_cast<uint32_t*>(&ol[base]) = lp;
            }
        }
    }
}

// ===========================================================================
// Fused attention (R13-proven): per block = (bh, 128 q-rows). 512 thr.
// Pass 1: E = exp(QK^T/8) -> attn (raw) + reg rowsums. K dbl-buffered.
// Pass 2: 32 K-chunks of 64 — read E (L2-hot), normalize in place, O = P@V.
// ===========================================================================
__global__ void __launch_bounds__(512) attn_fused_kernel(
    const __nv_bfloat16* __restrict__ qh, const __nv_bfloat16* __restrict__ ql,
    const __nv_bfloat16* __restrict__ kh, const __nv_bfloat16* __restrict__ kl,
    const __nv_bfloat16* __restrict__ vh, const __nv_bfloat16* __restrict__ vl,
    float* __restrict__ attn, float* __restrict__ out)
{
    extern __shared__ char smem[];
    const uint32_t sb = smem_u32(smem);
    const int tid = threadIdx.x, wid = tid >> 5, lane = tid & 31;
    const int mt_blk = blockIdx.x, bh = blockIdx.y;
    const int m0 = mt_blk * 128;

    const __nv_bfloat16* qhb = qh + ((size_t)bh * LSEQ + m0) * DH;
    const __nv_bfloat16* qlb = ql + ((size_t)bh * LSEQ + m0) * DH;
    const __nv_bfloat16* khb = kh + (size_t)bh * LSEQ * DH;
    const __nv_bfloat16* klb = kl + (size_t)bh * LSEQ * DH;
    const __nv_bfloat16* vhb = vh + (size_t)bh * LSEQ * DH;
    const __nv_bfloat16* vlb = vl + (size_t)bh * LSEQ * DH;
    float* apb = attn + ((size_t)bh * LSEQ + m0) * LSEQ;

    // ---- load Q + K(0) ----
    auto load_k = [&](int nt, int stage) {
        const int n0 = nt * 128;
        for (int i = tid; i < 1024; i += 512) {
            int r = i >> 3, c8 = (i & 7) * 8;
            uint32_t d = swz((uint32_t)0, r, c8 * 2);
            size_t ga = (size_t)(n0 + r) * DH + c8;
            cpasync16(sb + F_KH(stage) + d, &khb[ga]);
            cpasync16(sb + F_KL(stage) + d, &klb[ga]);
        }
        CP_COMMIT();
    };
    for (int i = tid; i < 1024; i += 512) {
        int r = i >> 3, c8 = (i & 7) * 8;
        uint32_t d = swz((uint32_t)0, r, c8 * 2);
        size_t ga = (size_t)r * DH + c8;
        cpasync16(sb + F_QH + d, &qhb[ga]);
        cpasync16(sb + F_QL + d, &qlb[ga]);
    }
    load_k(0, 0);

    // ---- Pass 1: 16 N-tiles ----
    const int m_base = (wid & 3) * 32, n_base = (wid >> 2) * 32;
    float sloc[2][2] = {};

    for (int nt = 0; nt < 16; nt++) {
        const int stage = nt & 1;
        if (nt + 1 < 16) { load_k(nt + 1, stage ^ 1); CP_WAIT(1); }
        else             { CP_WAIT(0); }
        __syncthreads();

        float C1[2][4][4] = {};
        mma_block_32(C1, sb + F_QH, sb + F_QL, sb + F_KH(stage), sb + F_KL(stage),
                     m_base, n_base, lane);

        const int n0 = nt * 128;
#pragma unroll
        for (int mt = 0; mt < 2; mt++)
#pragma unroll
            for (int ni = 0; ni < 4; ni++)
#pragma unroll
                for (int half = 0; half < 2; half++) {
                    float e0 = fast_exp8(C1[mt][ni][half * 2]);
                    float e1 = fast_exp8(C1[mt][ni][half * 2 + 1]);
                    sloc[mt][half] += e0 + e1;
                    int row = m_base + mt * 16 + (lane >> 2) + half * 8;
                    int col = n0 + n_base + ni * 8 + 2 * (lane & 3);
                    *reinterpret_cast<float2*>(&apb[(size_t)row * LSEQ + col]) =
                        make_float2(e0, e1);
                }
        __syncthreads();
    }

    // ---- rowsum ----
    float* RS = reinterpret_cast<float*>(smem + F_RS);
#pragma unroll
    for (int mt = 0; mt < 2; mt++)
#pragma unroll
        for (int half = 0; half < 2; half++) {
            float v = sloc[mt][half];
            v += __shfl_xor_sync(0xFFFFFFFFu, v, 1);
            v += __shfl_xor_sync(0xFFFFFFFFu, v, 2);
            if ((lane & 3) == 0) {
                int row = m_base + mt * 16 + (lane >> 2) + half * 8;
                RS[row * 4 + (wid >> 2)] = v;
            }
        }
    __syncthreads();
    float* srinv = reinterpret_cast<float*>(smem + F_RINV);
    if (tid < 128) {
        float s = RS[tid * 4 + 0] + RS[tid * 4 + 1] + RS[tid * 4 + 2] + RS[tid * 4 + 3];
        srinv[tid] = 1.0f / s;
    }
    __syncthreads();

    // ---- Pass 2: 32 K-chunks of 64 ----
    const int n_base2 = (wid >> 2) * 16;   // m_base reused
    const int er = tid >> 4, ec = (tid & 15) * 4;

    auto load_v = [&](int ck, int stage) {
        const int k0 = ck * 64;
        int i = tid;
        if (i < 512) {
            int r = i >> 3, c8 = (i & 7) * 8;
            uint32_t d = swz((uint32_t)0, r, c8 * 2);
            size_t ga = (size_t)(k0 + r) * DH + c8;
            cpasync16(sb + F_VH(stage) + d, &vhb[ga]);
            cpasync16(sb + F_VL(stage) + d, &vlb[ga]);
        }
        CP_COMMIT();
    };

    float4 Ereg[4];
#pragma unroll
    for (int j = 0; j < 4; j++)
        Ereg[j] = *reinterpret_cast<const float4*>(&apb[(size_t)(er + j * 32) * LSEQ + ec]);
    load_v(0, 0);

    float C2[2][2][4] = {};

    for (int ck = 0; ck < 32; ck++) {
        const int k0 = ck * 64;
        const int stage = ck & 1;
        if (ck + 1 < 32) load_v(ck + 1, stage ^ 1);

#pragma unroll
        for (int j = 0; j < 4; j++) {
            int r = er + j * 32;
            float4 e = Ereg[j];
            float ri = srinv[r];
            e.x *= ri; e.y *= ri; e.z *= ri; e.w *= ri;
            *reinterpret_cast<float4*>(&apb[(size_t)r * LSEQ + k0 + ec]) = e;
            uint32_t h0, l0, h1, l1;
            split2(e.x, e.y, h0, l0);
            split2(e.z, e.w, h1, l1);
            uint32_t d = swz((uint32_t)0, r, ec * 2);
            *reinterpret_cast<uint2*>(smem + F_PH + d) = make_uint2(h0, h1);
            *reinterpret_cast<uint2*>(smem + F_PL + d) = make_uint2(l0, l1);
        }
        if (ck + 1 < 32) { CP_WAIT(1); } else { CP_WAIT(0); }
        __syncthreads();

        if (ck + 1 < 32) {
#pragma unroll
            for (int j = 0; j < 4; j++)
                Ereg[j] = *reinterpret_cast<const float4*>(
                    &apb[(size_t)(er + j * 32) * LSEQ + (k0 + 64) + ec]);
        }

        const uint32_t vH = sb + F_VH(stage), vL = sb + F_VL(stage);
#pragma unroll
        for (int term = 0; term < 3; term++) {
            uint32_t As = sb + ((term == 2) ? F_PL : F_PH);
            uint32_t Bs = (term == 1) ? vL : vH;
#pragma unroll
            for (int ks = 0; ks < 4; ks++) {
                uint32_t a[2][4];
#pragma unroll
                for (int mt = 0; mt < 2; mt++)
                    ldsm4(a[mt], swz(As, m_base + mt * 16 + (lane & 15), ks * 32 + (lane >> 4) * 16));
                uint32_t b[2][2];
                const int mg = lane >> 3, rs = lane & 7;
                {
                    uint32_t r4[4];
                    int row = ks * 16 + (mg & 1) * 8 + rs;
                    int cb = (n_base2 + ((mg >= 2) ? 8 : 0)) * 2;
                    ldsm4t(r4, swz(Bs, row, cb));
                    b[0][0] = r4[0]; b[0][1] = r4[1];
                    b[1][0] = r4[2]; b[1][1] = r4[3];
                }
#pragma unroll
                for (int mt = 0; mt < 2; mt++)
#pragma unroll
                    for (int nt = 0; nt < 2; nt++)
                        mma16816(C2[mt][nt], a[mt], b[nt]);
            }
        }
        __syncthreads();
    }

    const int b = bh >> 4, h = bh & 15;
#pragma unroll
    for (int mt = 0; mt < 2; mt++)
#pragma unroll
        for (int nt = 0; nt < 2; nt++) {
            int n = n_base2 + nt * 8 + 2 * (lane & 3);
#pragma unroll
            for (int half = 0; half < 2; half++) {
                int m = m0 + m_base + mt * 16 + (lane >> 2) + half * 8;
                *reinterpret_cast<float2*>(&out[((size_t)b * LSEQ + m) * DM + h * DH + n]) =
                    make_float2(C2[mt][nt][half * 2], C2[mt][nt][half * 2 + 1]);
            }
        }
}

// ===========================================================================
extern "C" void kernel_launch(void* const* d_in, const int* in_sizes, int n_in,
                              void* d_out, int out_size) {
    const float* q_in = (const float*)d_in[0];
    const float* k_in = (const float*)d_in[1];
    const float* v_in = (const float*)d_in[2];
    const float* wq   = (const float*)d_in[3];
    const float* wk   = (const float*)d_in[4];
    const float* wv   = (const float*)d_in[5];

    __nv_bfloat16 *xh, *xl, *wh, *wl, *qh, *ql, *kh, *kl, *vh, *vl;
    float *attn_scratch, *out_scratch;
    cudaGetSymbolAddress((void**)&xh, g_xh);
    cudaGetSymbolAddress((void**)&xl, g_xl);
    cudaGetSymbolAddress((void**)&wh, g_wh);
    cudaGetSymbolAddress((void**)&wl, g_wl);
    cudaGetSymbolAddress((void**)&qh, g_qh);
    cudaGetSymbolAddress((void**)&ql, g_ql);
    cudaGetSymbolAddress((void**)&kh, g_kh);
    cudaGetSymbolAddress((void**)&kl, g_kl);
    cudaGetSymbolAddress((void**)&vh, g_vh);
    cudaGetSymbolAddress((void**)&vl, g_vl);
    cudaGetSymbolAddress((void**)&attn_scratch, g_attn_s);
    cudaGetSymbolAddress((void**)&out_scratch, g_outs);

    const long long out_elems  = (long long)BSZ * LSEQ * DM;
    const long long attn_elems = (long long)NBH * LSEQ * LSEQ;

    float* out_ptr  = (float*)d_out;
    float* attn_ptr = attn_scratch;
    long long osz = (long long)out_size;
    if (osz >= out_elems + attn_elems) {
        attn_ptr = (float*)d_out + out_elems;
    } else if (osz == attn_elems) {
        attn_ptr = (float*)d_out;
        out_ptr  = out_scratch;
    }

    cudaFuncSetAttribute(proj_kernel,       cudaFuncAttributeMaxDynamicSharedMemorySize, SMEM_PROJ);
    cudaFuncSetAttribute(attn_fused_kernel, cudaFuncAttributeMaxDynamicSharedMemorySize, SMEM_FUSED);

    convert_all_kernel<<<dim3(2048, 6), 256>>>(
        q_in, k_in, v_in, wq, wk, wv, xh, xl, wh, wl);

    proj_kernel<<<dim3(DM / 128, (BSZ * LSEQ) / 128, 3), 256, SMEM_PROJ>>>(
        xh, xl, wh, wl, qh, ql, kh, kl, vh, vl);

    attn_fused_kernel<<<dim3(16, NBH), 512, SMEM_FUSED>>>(
        qh, ql, kh, kl, vh, vl, attn_ptr, out_ptr);
}